// round 16
// baseline (speedup 1.0000x reference)
#include <cuda_runtime.h>
#include <cstdint>

typedef unsigned long long u64;

#define VOCAB   10000
#define EMB     256
#define UNITS   128
#define NG      512        // 4 * UNITS, gate order i,f,c,o
#define BATCH   256
#define SEQ     1024

#define NTHREADS 512
#define NBLOCKS  128       // 2 batch rows per block, one wave

// Precomputed gate table: G[v][c] = sum_e emb[v][e]*Wk[e][c] + b[c]  (20.5 MB)
__device__ float g_G[VOCAB * NG];

// ---------------- f32x2 helpers ----------------
__device__ __forceinline__ u64 fma2(u64 a, u64 b, u64 c) {
    u64 d;
    asm("fma.rn.f32x2 %0, %1, %2, %3;" : "=l"(d) : "l"(a), "l"(b), "l"(c));
    return d;
}
__device__ __forceinline__ u64 pk2(float x, float y) {
    u64 r;
    asm("mov.b64 %0, {%1, %2};" : "=l"(r) : "f"(x), "f"(y));
    return r;
}
__device__ __forceinline__ float2 upk2(u64 v) {
    float2 r;
    asm("mov.b64 {%0, %1}, %2;" : "=f"(r.x), "=f"(r.y) : "l"(v));
    return r;
}
__device__ __forceinline__ float sigmoidf(float x) {
    return __fdividef(1.0f, 1.0f + __expf(-x));
}

// ---------------- Kernel 1: G = emb @ Wk + b ----------------
#define VB 16
__global__ void __launch_bounds__(512)
gbuild_kernel(const float* __restrict__ emb, const float* __restrict__ Wk,
              const float* __restrict__ b)
{
    __shared__ float es[VB][EMB];
    const int c  = threadIdx.x;
    const int v0 = blockIdx.x * VB;

    for (int i = c; i < VB * EMB; i += 512)
        es[i / EMB][i % EMB] = emb[v0 * EMB + i];
    __syncthreads();

    float acc[VB];
#pragma unroll
    for (int v = 0; v < VB; v++) acc[v] = 0.0f;

    for (int e = 0; e < EMB; e += 4) {
        const float w0 = Wk[(e + 0) * NG + c];
        const float w1 = Wk[(e + 1) * NG + c];
        const float w2 = Wk[(e + 2) * NG + c];
        const float w3 = Wk[(e + 3) * NG + c];
#pragma unroll
        for (int v = 0; v < VB; v++) {
            float4 ev = *(const float4*)&es[v][e];
            acc[v] += ev.x * w0 + ev.y * w1 + ev.z * w2 + ev.w * w3;
        }
    }
    const float bc = b[c];
#pragma unroll
    for (int v = 0; v < VB; v++)
        g_G[(v0 + v) * NG + c] = acc[v] + bc;
}

// ---------------- Kernel 2: persistent LSTM recurrence ----------------
// 128 CTAs x 512 threads (16 warps -> 4/SMSP), 2 batch rows per CTA.
// Thread j: warp w=j>>5, lane l=j&31; kq = l>>3 (k-quarter), unit
// u = w*8 + (l&7). The thread computes partial z for ALL FOUR gate
// columns of its unit over k in [32kq, 32kq+32), both rows.
//
// Reduction (8 shfl): xor16 row-swap, then xor8 butterfly -> z for my row.
// Gate tail + G-gather + h store only on (l&8)==0 lanes.
// ONE __syncthreads per step (double-buffered h).
//
// Weights per thread: 64 f32x2 pairs; gates 0,1 (32 pairs, 64 regs) in
// registers, gates 2,3 (32 pairs = 16 ulonglong2) in smem per-lane 16B
// (conflict-free). vs R15: gate-2 first half moved regs->smem so total
// register demand fits under the 128-reg occupancy cap WITHOUT spills
// (R14/R15 showed regs==128 + L2 3.4-3.6% = hot-loop spill traffic).
//
// h double-buffered, pair-interleaved, 16B skew per k-quarter:
//   u64 idx = 34*kq + 2*lp + row   (lp = pair within quarter, 0..15)
#define WT_ENTRIES 16                        // ulonglong2 slots per thread
#define WT_BYTES  (WT_ENTRIES * NTHREADS * 16)    // 131072 B
#define HB_OFF    WT_BYTES
#define HB_STRIDE 136                        // u64 per h buffer (4*34)
#define HB_BYTES  (2 * HB_STRIDE * 8)        // 2176 B
#define XS_OFF    (HB_OFF + HB_BYTES)
#define SMEM_TOTAL (XS_OFF + 2 * SEQ * 4)

__global__ void __launch_bounds__(NTHREADS, 1)
lstm_kernel(const int* __restrict__ x, const float* __restrict__ Wr,
            const float* __restrict__ Wd, const float* __restrict__ bd,
            float* __restrict__ out)
{
    extern __shared__ char smem[];
    ulonglong2* Wt   = (ulonglong2*)smem;          // [16][512]
    u64*        hbuf = (u64*)(smem + HB_OFF);      // [2][136]
    int*        xs   = (int*)(smem + XS_OFF);

    const int j   = threadIdx.x;
    const int blk = blockIdx.x;
    const int l   = j & 31;
    const int kq  = l >> 3;                  // k-quarter 0..3
    const int u   = (j >> 5) * 8 + (l & 7);  // unit 0..127
    const int c0  = u, c1 = 128 + u, c2 = 256 + u, c3 = 384 + u;
    const int kb  = 32 * kq;                 // k base
    const int row = kq >> 1;                 // my gate-phase batch row
    const bool tailLane = ((l & 8) == 0);    // lanes that run the gate tail

    // ---- one-time setup ----
    for (int i = j; i < 2 * SEQ; i += NTHREADS) {
        int rr = i >> 10, tt = i & (SEQ - 1);
        xs[i] = x[(blk * 2 + rr) * SEQ + tt];
    }
    // register weights: gate0 pairs 0..15, gate1 pairs 0..15
    u64 wrA[16], wrB[16];
#pragma unroll
    for (int lp = 0; lp < 16; lp++) {
        const int k = kb + 2 * lp;
        wrA[lp] = pk2(Wr[k * NG + c0], Wr[(k + 1) * NG + c0]);
        wrB[lp] = pk2(Wr[k * NG + c1], Wr[(k + 1) * NG + c1]);
    }
    // smem weights: m 0..7  = gate2 pairs {2m, 2m+1};
    //               m 8..15 = gate3 pairs {2(m-8), 2(m-8)+1}
    for (int m = 0; m < 8; m++) {
        const int k = kb + 2 * (2 * m);
        ulonglong2 wv;
        wv.x = pk2(Wr[k * NG + c2],       Wr[(k + 1) * NG + c2]);
        wv.y = pk2(Wr[(k + 2) * NG + c2], Wr[(k + 3) * NG + c2]);
        Wt[m * NTHREADS + j] = wv;
    }
    for (int m = 0; m < 8; m++) {
        const int k = kb + 2 * (2 * m);
        ulonglong2 wv;
        wv.x = pk2(Wr[k * NG + c3],       Wr[(k + 1) * NG + c3]);
        wv.y = pk2(Wr[(k + 2) * NG + c3], Wr[(k + 3) * NG + c3]);
        Wt[(8 + m) * NTHREADS + j] = wv;
    }
    // zero both h buffers
    for (int i = j; i < 2 * HB_STRIDE; i += NTHREADS) hbuf[i] = 0ull;
    __syncthreads();

    float c_state = 0.0f;                    // row `row` of unit u (tail lanes)

    for (int t = 0; t < SEQ; t++) {
        const u64* hbase = hbuf + ((t & 1) ? HB_STRIDE : 0) + 34 * kq;

        // prefetch gate-table gathers for (u, row) — tail lanes only
        float xg0 = 0.0f, xg1 = 0.0f, xg2 = 0.0f, xg3 = 0.0f;
        if (tailLane) {
            const int tok = xs[row * SEQ + t];
            const float* gr = g_G + (size_t)tok * NG + u;
            xg0 = gr[0];
            xg1 = gr[128];
            xg2 = gr[256];
            xg3 = gr[384];
        }

        // ---- FMA phase: 4 gates x 2 rows over my 16 k-pairs ----
        u64 a0r0 = 0ull, a0r1 = 0ull, a1r0 = 0ull, a1r1 = 0ull;
        u64 a2r0 = 0ull, a2r1 = 0ull, a3r0 = 0ull, a3r1 = 0ull;
#pragma unroll
        for (int i = 0; i < 8; i++) {
            // pairs lp=2i (hva) and lp=2i+1 (hvb); .x=row0, .y=row1
            ulonglong2 hva = *(const ulonglong2*)(hbase + 4 * i);
            ulonglong2 hvb = *(const ulonglong2*)(hbase + 4 * i + 2);

            a0r0 = fma2(wrA[2 * i],     hva.x, a0r0);
            a0r1 = fma2(wrA[2 * i],     hva.y, a0r1);
            a0r0 = fma2(wrA[2 * i + 1], hvb.x, a0r0);
            a0r1 = fma2(wrA[2 * i + 1], hvb.y, a0r1);

            a1r0 = fma2(wrB[2 * i],     hva.x, a1r0);
            a1r1 = fma2(wrB[2 * i],     hva.y, a1r1);
            a1r0 = fma2(wrB[2 * i + 1], hvb.x, a1r0);
            a1r1 = fma2(wrB[2 * i + 1], hvb.y, a1r1);

            ulonglong2 wv2 = Wt[i * NTHREADS + j];
            a2r0 = fma2(wv2.x, hva.x, a2r0);
            a2r1 = fma2(wv2.x, hva.y, a2r1);
            a2r0 = fma2(wv2.y, hvb.x, a2r0);
            a2r1 = fma2(wv2.y, hvb.y, a2r1);

            ulonglong2 wv3 = Wt[(8 + i) * NTHREADS + j];
            a3r0 = fma2(wv3.x, hva.x, a3r0);
            a3r1 = fma2(wv3.x, hva.y, a3r1);
            a3r0 = fma2(wv3.y, hvb.x, a3r0);
            a3r1 = fma2(wv3.y, hvb.y, a3r1);
        }

        // quarter-partials: p[g][r]
        float2 s;
        s = upk2(a0r0); const float p0r0 = s.x + s.y;
        s = upk2(a0r1); const float p0r1 = s.x + s.y;
        s = upk2(a1r0); const float p1r0 = s.x + s.y;
        s = upk2(a1r1); const float p1r1 = s.x + s.y;
        s = upk2(a2r0); const float p2r0 = s.x + s.y;
        s = upk2(a2r1); const float p2r1 = s.x + s.y;
        s = upk2(a3r0); const float p3r0 = s.x + s.y;
        s = upk2(a3r1); const float p3r1 = s.x + s.y;

        // round 1: xor16 ROW-SWAP — keep my-row partial, add partner's
        // my-row partial.
        const float own0 = row ? p0r1 : p0r0, oth0 = row ? p0r0 : p0r1;
        const float own1 = row ? p1r1 : p1r0, oth1 = row ? p1r0 : p1r1;
        const float own2 = row ? p2r1 : p2r0, oth2 = row ? p2r0 : p2r1;
        const float own3 = row ? p3r1 : p3r0, oth3 = row ? p3r0 : p3r1;
        float q0 = own0 + __shfl_xor_sync(0xffffffffu, oth0, 16);
        float q1 = own1 + __shfl_xor_sync(0xffffffffu, oth1, 16);
        float q2 = own2 + __shfl_xor_sync(0xffffffffu, oth2, 16);
        float q3 = own3 + __shfl_xor_sync(0xffffffffu, oth3, 16);

        // round 2: xor8 butterfly — combine the two k-halves of my row
        const float z0 = q0 + __shfl_xor_sync(0xffffffffu, q0, 8);
        const float z1 = q1 + __shfl_xor_sync(0xffffffffu, q1, 8);
        const float z2 = q2 + __shfl_xor_sync(0xffffffffu, q2, 8);
        const float z3 = q3 + __shfl_xor_sync(0xffffffffu, q3, 8);

        // ---- gate tail: only (l&8)==0 lanes (one per (u,row)) ----
        if (tailLane) {
            const float zi = z0 + xg0;
            const float zf = z1 + xg1;
            const float zc = z2 + xg2;
            const float zo = z3 + xg3;
            const float ig = sigmoidf(zi);
            const float fg = sigmoidf(zf);
            const float gg = fmaxf(zc, 0.0f);    // activation = relu
            const float og = sigmoidf(zo);
            c_state = fg * c_state + ig * gg;
            const float hn = og * fmaxf(c_state, 0.0f);

            // store h(t+1): pair kp=u>>1; float idx =
            //   68*(kp>>4) + 4*(kp&15) + 2*row + (u&1)
            float* hnx = (float*)(hbuf + (((t + 1) & 1) ? HB_STRIDE : 0));
            const int kp = u >> 1;
            hnx[68 * (kp >> 4) + 4 * (kp & 15) + 2 * row + (u & 1)] = hn;
        }
        __syncthreads();
    }

    // ---- dense head: final h lives in buffer 0 (SEQ is even) ----
    if (j < 4) {
        const int rr = j >> 1, oc = j & 1;
        const float* hb = (const float*)hbuf;     // buffer 0
        float acc = bd[oc];
        for (int uu = 0; uu < UNITS; uu++) {
            const int kp = uu >> 1;
            acc += hb[68 * (kp >> 4) + 4 * (kp & 15) + 2 * rr + (uu & 1)]
                 * Wd[uu * 2 + oc];
        }
        out[(blk * 2 + rr) * 2 + oc] = acc;
    }
}

// ---------------- launch ----------------
extern "C" void kernel_launch(void* const* d_in, const int* in_sizes, int n_in,
                              void* d_out, int out_size)
{
    const int*   x   = 0;
    const float *emb = 0, *Wk = 0, *Wr = 0, *bb = 0, *Wd = 0, *bd = 0;
    for (int i = 0; i < n_in; i++) {
        switch (in_sizes[i]) {                       // all sizes are distinct
            case BATCH * SEQ: x   = (const int*)  d_in[i]; break;  // 262144
            case VOCAB * EMB: emb = (const float*)d_in[i]; break;  // 2560000
            case EMB * NG:    Wk  = (const float*)d_in[i]; break;  // 131072
            case UNITS * NG:  Wr  = (const float*)d_in[i]; break;  // 65536
            case NG:          bb  = (const float*)d_in[i]; break;  // 512
            case UNITS * 2:   Wd  = (const float*)d_in[i]; break;  // 256
            case 2:           bd  = (const float*)d_in[i]; break;
        }
    }

    gbuild_kernel<<<VOCAB / VB, 512>>>(emb, Wk, bb);

    cudaFuncSetAttribute(lstm_kernel,
                         cudaFuncAttributeMaxDynamicSharedMemorySize, SMEM_TOTAL);
    lstm_kernel<<<NBLOCKS, NTHREADS, SMEM_TOTAL>>>(x, Wr, Wd, bd, (float*)d_out);
}

// round 17
// speedup vs baseline: 1.1770x; 1.1770x over previous
#include <cuda_runtime.h>
#include <cstdint>

typedef unsigned long long u64;

#define VOCAB   10000
#define EMB     256
#define UNITS   128
#define NG      512        // 4 * UNITS, gate order i,f,c,o
#define BATCH   256
#define SEQ     1024

#define NTHREADS 256
#define NBLOCKS  128       // 2 batch rows per block, one wave

// Precomputed gate table: G[v][c] = sum_e emb[v][e]*Wk[e][c] + b[c]  (20.5 MB)
__device__ float g_G[VOCAB * NG];

// ---------------- f32x2 helpers ----------------
__device__ __forceinline__ u64 fma2(u64 a, u64 b, u64 c) {
    u64 d;
    asm("fma.rn.f32x2 %0, %1, %2, %3;" : "=l"(d) : "l"(a), "l"(b), "l"(c));
    return d;
}
__device__ __forceinline__ u64 pk2(float x, float y) {
    u64 r;
    asm("mov.b64 %0, {%1, %2};" : "=l"(r) : "f"(x), "f"(y));
    return r;
}
__device__ __forceinline__ float2 upk2(u64 v) {
    float2 r;
    asm("mov.b64 {%0, %1}, %2;" : "=f"(r.x), "=f"(r.y) : "l"(v));
    return r;
}
__device__ __forceinline__ float sigmoidf(float x) {
    return __fdividef(1.0f, 1.0f + __expf(-x));
}

// ---------------- Kernel 1: G = emb @ Wk + b  (f32x2, v-paired) ----------------
// acc lanes = two adjacent embedding rows (v, v+1) for ONE column c.
// Weight pack (w,w) hoisted out of the v-loop; multiplier pair read as a
// single broadcast LDS.64 from the transposed es tile.
#define VB 16
__global__ void __launch_bounds__(512)
gbuild_kernel(const float* __restrict__ emb, const float* __restrict__ Wk,
              const float* __restrict__ b)
{
    __shared__ float esT[EMB][VB];          // transposed: esT[e][v], 16 KB
    const int c  = threadIdx.x;             // column 0..511
    const int v0 = blockIdx.x * VB;

    for (int i = c; i < VB * EMB; i += 512) {
        int v = i / EMB, e = i % EMB;
        esT[e][v] = emb[v0 * EMB + i];
    }
    __syncthreads();

    u64 acc2[VB / 2];
#pragma unroll
    for (int vp = 0; vp < VB / 2; vp++) acc2[vp] = 0ull;

    for (int e = 0; e < EMB; e += 4) {
        const u64 wp0 = pk2(Wk[(e + 0) * NG + c], Wk[(e + 0) * NG + c]);
        const u64 wp1 = pk2(Wk[(e + 1) * NG + c], Wk[(e + 1) * NG + c]);
        const u64 wp2 = pk2(Wk[(e + 2) * NG + c], Wk[(e + 2) * NG + c]);
        const u64 wp3 = pk2(Wk[(e + 3) * NG + c], Wk[(e + 3) * NG + c]);
#pragma unroll
        for (int vp = 0; vp < VB / 2; vp++) {
            acc2[vp] = fma2(wp0, *(const u64*)&esT[e + 0][2 * vp], acc2[vp]);
            acc2[vp] = fma2(wp1, *(const u64*)&esT[e + 1][2 * vp], acc2[vp]);
            acc2[vp] = fma2(wp2, *(const u64*)&esT[e + 2][2 * vp], acc2[vp]);
            acc2[vp] = fma2(wp3, *(const u64*)&esT[e + 3][2 * vp], acc2[vp]);
        }
    }
    const float bc = b[c];
#pragma unroll
    for (int vp = 0; vp < VB / 2; vp++) {
        float2 a = upk2(acc2[vp]);
        g_G[(size_t)(v0 + 2 * vp)     * NG + c] = a.x + bc;
        g_G[(size_t)(v0 + 2 * vp + 1) * NG + c] = a.y + bc;
    }
}

// ---------------- Kernel 2: persistent LSTM recurrence (R13 + rotation) --------
// 128 CTAs x 256 threads, 2 batch rows per CTA.
// Thread j: warp w=j>>5, lane l=j&31; kh = l>>4 (k-half), unit
// u = w*16 + (l&15). Thread computes partial z for ALL FOUR gate columns
// of its unit over k in [64kh, 64kh+64), both rows; one shfl.xor(16)
// row-swap exchange completes z; thread kh=r runs gates for row r.
// ONE __syncthreads per step (double-buffered h).
//
// NEW vs R13: warps 4-7 execute the 16 independent k-iterations rotated
// by 8 (8..15 then 0..7), so the two warps sharing an SMSP are never in
// the same LDS-burst region simultaneously -> LSU and FMA pipes overlap.
//
// Weights per thread: gates 0,1 full + gate 2 first half in registers
// (160 regs), gate 2 second half + gate 3 in smem per-lane ulonglong2.
// h double-buffered, pair-interleaved, 16B skew between k-halves.
#define WT_ENTRIES 24                       // ulonglong2 slots per thread
#define WT_BYTES  (WT_ENTRIES * NTHREADS * 16)   // 98304 B
#define HB_OFF    WT_BYTES
#define HB_STRIDE 132                       // u64 per h buffer (130 + pad)
#define HB_BYTES  (2 * HB_STRIDE * 8)       // 2112 B
#define XS_OFF    (HB_OFF + HB_BYTES)
#define SMEM_TOTAL (XS_OFF + 2 * SEQ * 4)

__global__ void __launch_bounds__(NTHREADS, 1)
lstm_kernel(const int* __restrict__ x, const float* __restrict__ Wr,
            const float* __restrict__ Wd, const float* __restrict__ bd,
            float* __restrict__ out)
{
    extern __shared__ char smem[];
    ulonglong2* Wt   = (ulonglong2*)smem;          // [24][256]
    u64*        hbuf = (u64*)(smem + HB_OFF);      // [2][132]
    int*        xs   = (int*)(smem + XS_OFF);

    const int j   = threadIdx.x;
    const int blk = blockIdx.x;
    const int l   = j & 31;
    const int kh  = l >> 4;                 // k-half 0/1
    const int u   = (j >> 5) * 16 + (l & 15);   // unit 0..127
    const int c0  = u, c1 = 128 + u, c2 = 256 + u, c3 = 384 + u;
    const int kb  = 64 * kh;                // k base
    const bool hiWarp = (j >= 128);         // warps 4-7: rotated iteration order

    // ---- one-time setup ----
    for (int i = j; i < 2 * SEQ; i += NTHREADS) {
        int row = i >> 10, tt = i & (SEQ - 1);
        xs[i] = x[(blk * 2 + row) * SEQ + tt];
    }
    // register weights: gates 0,1 all 32 pairs; gate 2 pairs 0..15
    u64 wr0[32], wr1[32], wr2[16];
#pragma unroll
    for (int kk = 0; kk < 32; kk++) {
        const int k = kb + 2 * kk;
        wr0[kk] = pk2(Wr[k * NG + c0], Wr[(k + 1) * NG + c0]);
        wr1[kk] = pk2(Wr[k * NG + c1], Wr[(k + 1) * NG + c1]);
    }
#pragma unroll
    for (int kk = 0; kk < 16; kk++) {
        const int k = kb + 2 * kk;
        wr2[kk] = pk2(Wr[k * NG + c2], Wr[(k + 1) * NG + c2]);
    }
    // smem weights: Wt[m][j]: m 0..7 = gate2 pairs {16+2m,17+2m};
    //               m 8..23 = gate3 pairs {2(m-8), 2(m-8)+1}
    for (int m = 0; m < 8; m++) {
        const int k = kb + 2 * (16 + 2 * m);
        ulonglong2 wv;
        wv.x = pk2(Wr[k * NG + c2],       Wr[(k + 1) * NG + c2]);
        wv.y = pk2(Wr[(k + 2) * NG + c2], Wr[(k + 3) * NG + c2]);
        Wt[m * NTHREADS + j] = wv;
    }
    for (int m = 0; m < 16; m++) {
        const int k = kb + 2 * (2 * m);
        ulonglong2 wv;
        wv.x = pk2(Wr[k * NG + c3],       Wr[(k + 1) * NG + c3]);
        wv.y = pk2(Wr[(k + 2) * NG + c3], Wr[(k + 3) * NG + c3]);
        Wt[(8 + m) * NTHREADS + j] = wv;
    }
    // zero both h buffers
    for (int i = j; i < 2 * HB_STRIDE; i += NTHREADS) hbuf[i] = 0ull;
    __syncthreads();

    float c_state = 0.0f;                   // row kh of this unit

    for (int t = 0; t < SEQ; t++) {
        const u64* hbase = hbuf + ((t & 1) ? HB_STRIDE : 0) + 66 * kh;

        // prefetch gate-table gathers for (u, row kh)
        const int tok = xs[kh * SEQ + t];
        const float* gr = g_G + (size_t)tok * NG + u;
        const float xg0 = gr[0];
        const float xg1 = gr[128];
        const float xg2 = gr[256];
        const float xg3 = gr[384];

        // ---- FMA phase: 4 gates x 2 rows over my 32 k-pairs ----
        u64 a0r0 = 0ull, a0r1 = 0ull, a1r0 = 0ull, a1r1 = 0ull;
        u64 a2r0 = 0ull, a2r1 = 0ull, a3r0 = 0ull, a3r1 = 0ull;

#define FMA_ITER(II)                                                          \
        {                                                                     \
            ulonglong2 hva = *(const ulonglong2*)(hbase + 4 * (II));          \
            ulonglong2 hvb = *(const ulonglong2*)(hbase + 4 * (II) + 2);      \
            a0r0 = fma2(wr0[2 * (II)],     hva.x, a0r0);                      \
            a0r1 = fma2(wr0[2 * (II)],     hva.y, a0r1);                      \
            a0r0 = fma2(wr0[2 * (II) + 1], hvb.x, a0r0);                      \
            a0r1 = fma2(wr0[2 * (II) + 1], hvb.y, a0r1);                      \
            a1r0 = fma2(wr1[2 * (II)],     hva.x, a1r0);                      \
            a1r1 = fma2(wr1[2 * (II)],     hva.y, a1r1);                      \
            a1r0 = fma2(wr1[2 * (II) + 1], hvb.x, a1r0);                      \
            a1r1 = fma2(wr1[2 * (II) + 1], hvb.y, a1r1);                      \
            u64 w2a, w2b;                                                     \
            if ((II) < 8) { w2a = wr2[2 * (II)]; w2b = wr2[2 * (II) + 1]; }   \
            else {                                                            \
                ulonglong2 wv = Wt[((II) - 8) * NTHREADS + j];                \
                w2a = wv.x; w2b = wv.y;                                       \
            }                                                                 \
            a2r0 = fma2(w2a, hva.x, a2r0);                                    \
            a2r1 = fma2(w2a, hva.y, a2r1);                                    \
            a2r0 = fma2(w2b, hvb.x, a2r0);                                    \
            a2r1 = fma2(w2b, hvb.y, a2r1);                                    \
            ulonglong2 wv3 = Wt[(8 + (II)) * NTHREADS + j];                   \
            a3r0 = fma2(wv3.x, hva.x, a3r0);                                  \
            a3r1 = fma2(wv3.x, hva.y, a3r1);                                  \
            a3r0 = fma2(wv3.y, hvb.x, a3r0);                                  \
            a3r1 = fma2(wv3.y, hvb.y, a3r1);                                  \
        }

        if (!hiWarp) {
            FMA_ITER(0)  FMA_ITER(1)  FMA_ITER(2)  FMA_ITER(3)
            FMA_ITER(4)  FMA_ITER(5)  FMA_ITER(6)  FMA_ITER(7)
            FMA_ITER(8)  FMA_ITER(9)  FMA_ITER(10) FMA_ITER(11)
            FMA_ITER(12) FMA_ITER(13) FMA_ITER(14) FMA_ITER(15)
        } else {
            FMA_ITER(8)  FMA_ITER(9)  FMA_ITER(10) FMA_ITER(11)
            FMA_ITER(12) FMA_ITER(13) FMA_ITER(14) FMA_ITER(15)
            FMA_ITER(0)  FMA_ITER(1)  FMA_ITER(2)  FMA_ITER(3)
            FMA_ITER(4)  FMA_ITER(5)  FMA_ITER(6)  FMA_ITER(7)
        }
#undef FMA_ITER

        // half-sums: p[g][row]
        float2 s;
        s = upk2(a0r0); const float p0r0 = s.x + s.y;
        s = upk2(a0r1); const float p0r1 = s.x + s.y;
        s = upk2(a1r0); const float p1r0 = s.x + s.y;
        s = upk2(a1r1); const float p1r1 = s.x + s.y;
        s = upk2(a2r0); const float p2r0 = s.x + s.y;
        s = upk2(a2r1); const float p2r1 = s.x + s.y;
        s = upk2(a3r0); const float p3r0 = s.x + s.y;
        s = upk2(a3r1); const float p3r1 = s.x + s.y;

        // exchange: send my partial for the OTHER row; receive partner's
        // partial for MY row; add -> full z for row kh.
        const float own0 = kh ? p0r1 : p0r0, oth0 = kh ? p0r0 : p0r1;
        const float own1 = kh ? p1r1 : p1r0, oth1 = kh ? p1r0 : p1r1;
        const float own2 = kh ? p2r1 : p2r0, oth2 = kh ? p2r0 : p2r1;
        const float own3 = kh ? p3r1 : p3r0, oth3 = kh ? p3r0 : p3r1;
        const float z0 = own0 + __shfl_xor_sync(0xffffffffu, oth0, 16);
        const float z1 = own1 + __shfl_xor_sync(0xffffffffu, oth1, 16);
        const float z2 = own2 + __shfl_xor_sync(0xffffffffu, oth2, 16);
        const float z3 = own3 + __shfl_xor_sync(0xffffffffu, oth3, 16);

        // ---- gates for (unit u, row kh) ----
        const float zi = z0 + xg0;
        const float zf = z1 + xg1;
        const float zc = z2 + xg2;
        const float zo = z3 + xg3;
        const float ig = sigmoidf(zi);
        const float fg = sigmoidf(zf);
        const float gg = fmaxf(zc, 0.0f);   // activation = relu
        const float og = sigmoidf(zo);
        c_state = fg * c_state + ig * gg;
        const float hn = og * fmaxf(c_state, 0.0f);

        // store h(t+1): kp = u>>1; float idx = 4*kp + 2*kh + (u&1) + 4*(kp>=32)
        float* hnx = (float*)(hbuf + (((t + 1) & 1) ? HB_STRIDE : 0));
        hnx[4 * (u >> 1) + 2 * kh + (u & 1) + ((u >= 64) ? 4 : 0)] = hn;
        __syncthreads();
    }

    // ---- dense head: final h lives in buffer 0 (SEQ is even) ----
    if (j < 4) {
        const int rr = j >> 1, oc = j & 1;
        const float* hb = (const float*)hbuf;     // buffer 0
        float acc = bd[oc];
        for (int uu = 0; uu < UNITS; uu++)
            acc += hb[4 * (uu >> 1) + 2 * rr + (uu & 1) + ((uu >= 64) ? 4 : 0)]
                 * Wd[uu * 2 + oc];
        out[(blk * 2 + rr) * 2 + oc] = acc;
    }
}

// ---------------- launch ----------------
extern "C" void kernel_launch(void* const* d_in, const int* in_sizes, int n_in,
                              void* d_out, int out_size)
{
    const int*   x   = 0;
    const float *emb = 0, *Wk = 0, *Wr = 0, *bb = 0, *Wd = 0, *bd = 0;
    for (int i = 0; i < n_in; i++) {
        switch (in_sizes[i]) {                       // all sizes are distinct
            case BATCH * SEQ: x   = (const int*)  d_in[i]; break;  // 262144
            case VOCAB * EMB: emb = (const float*)d_in[i]; break;  // 2560000
            case EMB * NG:    Wk  = (const float*)d_in[i]; break;  // 131072
            case UNITS * NG:  Wr  = (const float*)d_in[i]; break;  // 65536
            case NG:          bb  = (const float*)d_in[i]; break;  // 512
            case UNITS * 2:   Wd  = (const float*)d_in[i]; break;  // 256
            case 2:           bd  = (const float*)d_in[i]; break;
        }
    }

    gbuild_kernel<<<VOCAB / VB, 512>>>(emb, Wk, bb);

    cudaFuncSetAttribute(lstm_kernel,
                         cudaFuncAttributeMaxDynamicSharedMemorySize, SMEM_TOTAL);
    lstm_kernel<<<NBLOCKS, NTHREADS, SMEM_TOTAL>>>(x, Wr, Wd, bd, (float*)d_out);
}